// round 3
// baseline (speedup 1.0000x reference)
#include <cuda_runtime.h>

// Problem constants (from reference setup_inputs):
//   poses:       (4, 16, 16, 32, 4, 4)  float32
//   activations: (4, 16, 16, 32, 1, 1)  float32
//   pose_kernel: (3, 3, 32, 32, 4, 4)   float32
//   votes out:   (4, 14, 14, 3, 3, 32, 32, 4, 4)
//   act out:     (4, 14, 14, 3, 3, 32, 1, 1, 1)   appended after votes
// No contraction in the einsum -> votes is an elementwise broadcast product:
//   votes[b,h,w,x,y,i,o,m,n] = poses[b,h+x,w+y,i,m,n] * pk[x,y,i,o,m,n]

constexpr int B  = 4;
constexpr int H  = 16;
constexpr int W  = 16;
constexpr int OH = 14;
constexpr int OW = 14;
constexpr int KS = 3;
constexpr int IC = 32;
constexpr int OC = 32;
constexpr int AT = 16;   // 4x4 pose atom

constexpr int NCOMBO = KS * KS * IC;           // 288 (x,y,i) combos
constexpr int NSP    = B * OH * OW;            // 784 spatial positions
constexpr int SPT    = 8;                      // spatial tuples per warp
constexpr int NCHUNK = NSP / SPT;              // 98
constexpr int NPOS   = NCOMBO * NSP;           // 225792 tuples
constexpr long long VOTES_ELEMS = (long long)NPOS * OC * AT; // 115,605,504

// One warp per (combo, spatial-chunk). The warp loads its 512B pose_kernel
// slice (lane's float4 per quarter) into registers ONCE, then streams SPT
// tuples: per tuple only a 1-wavefront pose broadcast load + 4 contiguous
// 512B stores (+ lane-0 act element). This removes the per-tuple kernel
// reload that made L1tex the binding pipe in R2 (L1=79% > DRAM=76%).
__global__ __launch_bounds__(256) void fused_kernel(
    const float* __restrict__ poses,
    const float* __restrict__ act,
    const float* __restrict__ pk,
    float* __restrict__ votes_out,
    float* __restrict__ act_out)
{
    int gw   = (blockIdx.x * blockDim.x + threadIdx.x) >> 5;
    int lane = threadIdx.x & 31;
    if (gw >= NCOMBO * NCHUNK) return;

    // Same-combo warps adjacent -> a block's 8 warps share the k slice (L1 hit).
    int combo = gw / NCHUNK;
    int chunk = gw - combo * NCHUNK;

    int i = combo & 31;
    int xy = combo >> 5;          // x*KS + y
    int y = xy % KS;
    int x = xy / KS;

    // Load this warp's kernel slice into registers: float4 #(j*32+lane) of
    // the 128-float4 [o][m][n] block for (x,y,i).
    const float4* kv = reinterpret_cast<const float4*>(pk)
                     + (long long)combo * (OC * AT / 4);
    float4 k0 = kv[0 * 32 + lane];
    float4 k1 = kv[1 * 32 + lane];
    float4 k2 = kv[2 * 32 + lane];
    float4 k3 = kv[3 * 32 + lane];

    const float4* pv_base = reinterpret_cast<const float4*>(poses);
    int lane4 = lane & 3;

#pragma unroll
    for (int s = 0; s < SPT; ++s) {
        int sp = chunk * SPT + s;                 // (b*OH + h)*OW + w
        int w  = sp % OW;
        int t  = sp / OW;
        int h  = t % OH;
        int b  = t / OH;

        int src_pix = ((b * H + (h + x)) * W + (w + y)) * IC + i;

        // pose atom: 64B-aligned 64B span -> single L1 wavefront (broadcast)
        float4 p = pv_base[src_pix * 4 + lane4];

        // output block for tuple (sp, combo): 128 contiguous float4s
        long long tuple = (long long)sp * NCOMBO + combo;
        float4* ov = reinterpret_cast<float4*>(votes_out) + tuple * (OC * AT / 4);

        float4 o0, o1, o2, o3;
        o0.x = p.x * k0.x; o0.y = p.y * k0.y; o0.z = p.z * k0.z; o0.w = p.w * k0.w;
        o1.x = p.x * k1.x; o1.y = p.y * k1.y; o1.z = p.z * k1.z; o1.w = p.w * k1.w;
        o2.x = p.x * k2.x; o2.y = p.y * k2.y; o2.z = p.z * k2.z; o2.w = p.w * k2.w;
        o3.x = p.x * k3.x; o3.y = p.y * k3.y; o3.z = p.z * k3.z; o3.w = p.w * k3.w;

        ov[0 * 32 + lane] = o0;
        ov[1 * 32 + lane] = o1;
        ov[2 * 32 + lane] = o2;
        ov[3 * 32 + lane] = o3;

        if (lane == 0) {
            act_out[tuple] = act[src_pix];
        }
    }
}

extern "C" void kernel_launch(void* const* d_in, const int* in_sizes, int n_in,
                              void* d_out, int out_size)
{
    const float* poses = (const float*)d_in[0];
    const float* acts  = (const float*)d_in[1];
    const float* pk    = (const float*)d_in[2];
    float* out = (float*)d_out;

    int nwarps = NCOMBO * NCHUNK;          // 28224
    int threads = 256;
    int blocks = (nwarps * 32 + threads - 1) / threads;
    fused_kernel<<<blocks, threads>>>(poses, acts, pk, out, out + VOTES_ELEMS);
}

// round 4
// speedup vs baseline: 1.1465x; 1.1465x over previous
#include <cuda_runtime.h>

// Problem constants (from reference setup_inputs):
//   poses:       (4, 16, 16, 32, 4, 4)  float32
//   activations: (4, 16, 16, 32, 1, 1)  float32
//   pose_kernel: (3, 3, 32, 32, 4, 4)   float32
//   votes out:   (4, 14, 14, 3, 3, 32, 32, 4, 4)
//   act out:     (4, 14, 14, 3, 3, 32, 1, 1, 1)   appended after votes
// No contraction in the einsum -> votes is an elementwise broadcast product:
//   votes[b,h,w,x,y,i,o,m,n] = poses[b,h+x,w+y,i,m,n] * pk[x,y,i,o,m,n]

constexpr int B  = 4;
constexpr int H  = 16;
constexpr int W  = 16;
constexpr int OH = 14;
constexpr int OW = 14;
constexpr int KS = 3;
constexpr int IC = 32;
constexpr int OC = 32;
constexpr int AT = 16;   // 4x4 pose atom

constexpr int NCOMBO = KS * KS * IC;            // 288 (x,y,i) combos
constexpr int NSP    = B * OH * OW;             // 784 spatial positions
constexpr int NPOS   = NCOMBO * NSP;            // 225792 tuples
constexpr int SPT    = 8;                       // tuples per warp
constexpr int NW     = NPOS / SPT;              // 28224 warps
constexpr int SP_STEP = NSP / SPT;              // 98 (NW = SP_STEP * NCOMBO)
constexpr long long VOTES_ELEMS = (long long)NPOS * OC * AT; // 115,605,504

// Grid-stride tuple mapping: warp gw handles tuples {gw + s*NW, s=0..7}.
// Since NW % NCOMBO == 0, combo = gw % NCOMBO is invariant across s, so the
// 512B pose_kernel slice is loaded into registers ONCE per warp. Meanwhile
// each iteration s the full warp population writes tuples [s*NW,(s+1)*NW) --
// one contiguous 57.8MB sweep in ascending order (adjacent warps -> adjacent
// 512B blocks), preserving R2's DRAM/TLB write locality that R3's combo-major
// mapping destroyed. Stores use .cs (evict-first) so L2 keeps the small
// read-side working set (poses 2MB + pk 0.6MB) resident.
__global__ __launch_bounds__(256) void fused_kernel(
    const float* __restrict__ poses,
    const float* __restrict__ act,
    const float* __restrict__ pk,
    float* __restrict__ votes_out,
    float* __restrict__ act_out)
{
    int gw   = (blockIdx.x * blockDim.x + threadIdx.x) >> 5;
    int lane = threadIdx.x & 31;
    if (gw >= NW) return;

    int combo   = gw % NCOMBO;
    int sp_base = gw / NCOMBO;          // 0..97

    int i  = combo & 31;
    int xy = combo >> 5;                // x*KS + y
    int y  = xy % KS;
    int x  = xy / KS;

    // Cache this combo's kernel slice in registers: float4 #(j*32+lane) of
    // the 128-float4 [o][m][n] block.
    const float4* kv = reinterpret_cast<const float4*>(pk)
                     + (long long)combo * (OC * AT / 4);
    float4 k0 = kv[0 * 32 + lane];
    float4 k1 = kv[1 * 32 + lane];
    float4 k2 = kv[2 * 32 + lane];
    float4 k3 = kv[3 * 32 + lane];

    const float4* pv_base = reinterpret_cast<const float4*>(poses);
    int lane4 = lane & 3;

#pragma unroll
    for (int s = 0; s < SPT; ++s) {
        int sp = sp_base + s * SP_STEP;           // (b*OH + h)*OW + w
        int w  = sp % OW;
        int t  = sp / OW;
        int h  = t % OH;
        int b  = t / OH;

        int src_pix = ((b * H + (h + x)) * W + (w + y)) * IC + i;

        // pose atom: 64B-aligned 64B span -> single broadcast wavefront
        float4 p = pv_base[src_pix * 4 + lane4];

        long long tuple = (long long)sp * NCOMBO + combo;   // == gw + s*NW
        float4* ov = reinterpret_cast<float4*>(votes_out) + tuple * (OC * AT / 4);

        float4 o0, o1, o2, o3;
        o0.x = p.x * k0.x; o0.y = p.y * k0.y; o0.z = p.z * k0.z; o0.w = p.w * k0.w;
        o1.x = p.x * k1.x; o1.y = p.y * k1.y; o1.z = p.z * k1.z; o1.w = p.w * k1.w;
        o2.x = p.x * k2.x; o2.y = p.y * k2.y; o2.z = p.z * k2.z; o2.w = p.w * k2.w;
        o3.x = p.x * k3.x; o3.y = p.y * k3.y; o3.z = p.z * k3.z; o3.w = p.w * k3.w;

        __stcs(&ov[0 * 32 + lane], o0);
        __stcs(&ov[1 * 32 + lane], o1);
        __stcs(&ov[2 * 32 + lane], o2);
        __stcs(&ov[3 * 32 + lane], o3);

        if (lane == 0) {
            act_out[tuple] = act[src_pix];
        }
    }
}

extern "C" void kernel_launch(void* const* d_in, const int* in_sizes, int n_in,
                              void* d_out, int out_size)
{
    const float* poses = (const float*)d_in[0];
    const float* acts  = (const float*)d_in[1];
    const float* pk    = (const float*)d_in[2];
    float* out = (float*)d_out;

    int threads = 256;
    int blocks = (NW * 32 + threads - 1) / threads;   // 3528
    fused_kernel<<<blocks, threads>>>(poses, acts, pk, out, out + VOTES_ELEMS);
}